// round 5
// baseline (speedup 1.0000x reference)
#include <cuda_runtime.h>
#include <cuda_fp16.h>
#include <cstdint>

#define THREADS 512
static constexpr int BATCH  = 131072;
static constexpr int DDIM   = 128;
static constexpr int TILE_M = 128;
static constexpr int NTILES = BATCH / TILE_M;   // 1024
static constexpr int PITCH  = 272;              // 128 fp16 (256B) + 16B pad -> conflict-free ldmatrix

// ---- SMEM layout (bytes). A fp16 double-buffered; B single fp16; warp-private epilogue staging. ----
static constexpr int SM_A0   = 0;               // 128 x PITCH = 34816
static constexpr int SM_A1   = 34816;
static constexpr int SM_B    = 69632;           // 256 x PITCH = 69632
static constexpr int SM_BIAS = 139264;          // 256 floats = 1024
static constexpr int SM_STG  = 140288;          // 16 warps x 2048B = 32768
static constexpr int SMEM_TOTAL = 140288 + 32768;   // 173056

// ---------------- helpers ----------------
__device__ __forceinline__ uint32_t smem_u32(const void* p){
    uint32_t a;
    asm("{ .reg .u64 t; cvta.to.shared.u64 t, %1; cvt.u32.u64 %0, t; }" : "=r"(a) : "l"(p));
    return a;
}
__device__ __forceinline__ void ldsm4(uint32_t* r, uint32_t addr){
    asm volatile("ldmatrix.sync.aligned.m8n8.x4.shared.b16 {%0,%1,%2,%3}, [%4];"
        : "=r"(r[0]), "=r"(r[1]), "=r"(r[2]), "=r"(r[3]) : "r"(addr));
}
__device__ __forceinline__ void mma16816(float* c, const uint32_t* a, uint32_t b0, uint32_t b1){
    asm("mma.sync.aligned.m16n8k16.row.col.f32.f16.f16.f32 "
        "{%0,%1,%2,%3}, {%4,%5,%6,%7}, {%8,%9}, {%0,%1,%2,%3};"
        : "+f"(c[0]), "+f"(c[1]), "+f"(c[2]), "+f"(c[3])
        : "r"(a[0]), "r"(a[1]), "r"(a[2]), "r"(a[3]), "r"(b0), "r"(b1));
}
__device__ __forceinline__ uint32_t pack_h2(float lo, float hi){
    __half2 h = __floats2half2_rn(lo, hi);
    return *reinterpret_cast<uint32_t*>(&h);
}
__device__ __forceinline__ void sts64(uint32_t addr, float x, float y){
    asm volatile("st.shared.v2.f32 [%0], {%1, %2};" :: "r"(addr), "f"(x), "f"(y) : "memory");
}
__device__ __forceinline__ float4 lds128(uint32_t addr){
    float4 v;
    asm volatile("ld.shared.v4.f32 {%0,%1,%2,%3}, [%4];"
        : "=f"(v.x), "=f"(v.y), "=f"(v.z), "=f"(v.w) : "r"(addr));
    return v;
}

// ---------------- tile helpers ----------------
__device__ __forceinline__ void prefetch_tile(const float* __restrict__ state, int t, int tid, float4* v){
    const float4* p = reinterpret_cast<const float4*>(state) + (size_t)t * (TILE_M * DDIM / 4);
    #pragma unroll
    for (int k = 0; k < 8; k++) v[k] = p[tid + THREADS * k];
}

// fp32 -> fp16 conversion of the 128x128 state tile into A smem (row pitch 272B).
__device__ __forceinline__ void convert_tile(char* sm, int buf, int tid, const float4* v){
    const int AH = buf ? SM_A1 : SM_A0;
    #pragma unroll
    for (int k = 0; k < 8; k++){
        int j  = tid + THREADS * k;           // float4 index within tile
        int r  = j >> 5;                      // row (32 float4 per row)
        int cb = (j & 31) * 8;                // byte col within 256B of fp16 data
        uint32_t off = (uint32_t)r * PITCH + cb;
        float4 f = v[k];
        uint32_t h0 = pack_h2(f.x, f.y);
        uint32_t h1 = pack_h2(f.z, f.w);
        *reinterpret_cast<uint2*>(sm + AH + off) = make_uint2(h0, h1);
    }
}

// ---------------- kernel ----------------
__global__ void __launch_bounds__(THREADS, 1)
lfm_kernel(const float* __restrict__ state, const float* __restrict__ Wt,
           const float* __restrict__ bias,  float* __restrict__ out)
{
    extern __shared__ char sm[];
    uint32_t sbase = smem_u32(sm);
    const int tid  = threadIdx.x;
    const int wid  = tid >> 5;
    const int lane = tid & 31;
    const int wm   = wid & 3;       // warp m-block (32 rows each)
    const int wn   = wid >> 2;      // warp n-block (64 cols each)

    // ---- one-time: W[n][o][d] -> fp16 B smem (row index = o*128+n, k=d), bias to smem ----
    for (int idx = tid; idx < 128 * 128; idx += THREADS){
        int n = idx >> 7, d = idx & 127;
        #pragma unroll
        for (int o = 0; o < 2; o++){
            float w = Wt[(size_t)n * 256 + o * 128 + d];
            uint32_t off = (uint32_t)(o * 128 + n) * PITCH + d * 2;
            *reinterpret_cast<__half*>(sm + SM_B + off) = __float2half_rn(w);
        }
    }
    for (int idx = tid; idx < 256; idx += THREADS){
        int o = idx >> 7, n = idx & 127;
        reinterpret_cast<float*>(sm + SM_BIAS)[idx] = bias[n * 2 + o];
    }

    // per-lane ldmatrix sub-offsets
    const uint32_t aoff = (uint32_t)((lane & 7) + ((lane >> 3) & 1) * 8) * PITCH + ((lane >> 4) & 1) * 16;
    const uint32_t boff = (uint32_t)((lane & 7) + ((lane >> 4) & 1) * 8) * PITCH + ((lane >> 3) & 1) * 16;
    const uint32_t baseA0 = sbase + SM_A0 + (uint32_t)(wm * 32) * PITCH + aoff;
    const uint32_t baseB  = sbase + SM_B  + (uint32_t)(wn * 64) * PITCH + boff;

    const int bid = blockIdx.x, grid = gridDim.x;
    const int nt  = (NTILES - bid + grid - 1) / grid;   // >= 1 since grid <= NTILES

    // Prologue: load + convert first tile into buffer 0
    float4 v[8];
    prefetch_tile(state, bid, tid, v);
    convert_tile(sm, 0, tid, v);
    __syncthreads();

    // Bias fragments -> registers (constant across tiles)
    const int o_half = wn >> 1;
    float bR0[8], bR1[8];
    {
        const float* bias_sm = reinterpret_cast<const float*>(sm + SM_BIAS);
        #pragma unroll
        for (int nj = 0; nj < 8; nj++){
            int cgb = (wn & 1) * 64 + nj * 8 + 2 * (lane & 3) + (o_half << 7);
            bR0[nj] = bias_sm[cgb];
            bR1[nj] = bias_sm[cgb + 1];
        }
    }

    const size_t out_half = (size_t)BATCH * DDIM;
    const uint32_t wstg = sbase + SM_STG + (uint32_t)wid * 2048;   // warp-private staging: 8 rows x 256B

    // staging addresses (XOR-swizzled word columns; degree<=2 STS, floor-rate LDS)
    const int     rr_sts  = lane >> 2;                      // staging row for STS
    const uint32_t sw_rot = (uint32_t)(rr_sts << 3);        // (rr&7)<<3 word-XOR
    const int     rr_ld   = lane >> 4;                      // 0/1: row parity for LDS/STG
    const int     cw0     = 4 * (lane & 15);                // word col for LDS/STG (16B)

    int cur = 0;
    for (int i = 0; i < nt; i++){
        const int  t   = bid + i * grid;
        const bool nxt = (i + 1) < nt;

        const uint32_t bA = baseA0 + (uint32_t)(cur ? SM_A1 : 0);

        float acc[2][8][4];
        #pragma unroll
        for (int mt = 0; mt < 2; mt++)
            #pragma unroll
            for (int nj = 0; nj < 8; nj++)
                #pragma unroll
                for (int e = 0; e < 4; e++) acc[mt][nj][e] = 0.f;

        // ---- K loop: 8 steps of k16, single fp16 term ----
        #pragma unroll
        for (int ks = 0; ks < 8; ks++){
            uint32_t a0[4], a1[4];
            ldsm4(a0, bA + ks * 32);
            ldsm4(a1, bA + 16 * PITCH + ks * 32);
            #pragma unroll
            for (int np = 0; np < 4; np++){        // pairs of n8 tiles
                uint32_t bw[4];
                ldsm4(bw, baseB + (uint32_t)(np * 16) * PITCH + ks * 32);
                mma16816(acc[0][2*np],   a0, bw[0], bw[1]);
                mma16816(acc[1][2*np],   a1, bw[0], bw[1]);
                mma16816(acc[0][2*np+1], a0, bw[2], bw[3]);
                mma16816(acc[1][2*np+1], a1, bw[2], bw[3]);
            }
        }

        // Prefetch next tile's state; DRAM latency hidden behind epilogue.
        if (nxt) prefetch_tile(state, t + grid, tid, v);

        // ---- restaged epilogue: fragments -> swizzled staging -> coalesced STG.128 ----
        {
            float* outhp = out + (o_half ? out_half : 0)
                         + ((size_t)t * TILE_M + wm * 32) * DDIM + (wn & 1) * 64;
            #pragma unroll
            for (int g = 0; g < 4; g++){               // 8-row groups: (mt, half)
                const int mt = g >> 1, half = g & 1;
                // STS: 8 nj x float2 (bias added)
                #pragma unroll
                for (int nj = 0; nj < 8; nj++){
                    uint32_t cw  = (uint32_t)(nj * 8 + 2 * (lane & 3));
                    uint32_t adr = wstg + (uint32_t)rr_sts * 256 + ((cw ^ sw_rot) << 2);
                    sts64(adr, acc[mt][nj][2*half]     + bR0[nj],
                               acc[mt][nj][2*half + 1] + bR1[nj]);
                }
                __syncwarp();
                // LDS.128 row-contiguous + STG.128 coalesced (2 rows per instr)
                #pragma unroll
                for (int j = 0; j < 4; j++){
                    int rr = 2 * j + rr_ld;
                    uint32_t adr = wstg + (uint32_t)rr * 256 + (((uint32_t)cw0 ^ (uint32_t)(rr << 3)) << 2);
                    float4 val = lds128(adr);
                    int gr = mt * 16 + half * 8 + rr;
                    *reinterpret_cast<float4*>(outhp + (size_t)gr * DDIM + cw0) = val;
                }
                __syncwarp();                          // staging reused by next group
            }
        }

        // Refill the other A buffer, then one sync before the next K-loop reads it.
        if (nxt){
            convert_tile(sm, cur ^ 1, tid, v);
            __syncthreads();
        }
        cur ^= 1;
    }
}

extern "C" void kernel_launch(void* const* d_in, const int* in_sizes, int n_in,
                              void* d_out, int out_size){
    (void)in_sizes; (void)n_in; (void)out_size;
    const float* state = (const float*)d_in[0];
    const float* W     = (const float*)d_in[1];
    const float* b     = (const float*)d_in[2];
    float* out = (float*)d_out;

    int dev = 0, sms = 148;
    cudaGetDevice(&dev);
    cudaDeviceGetAttribute(&sms, cudaDevAttrMultiProcessorCount, dev);
    if (sms < 1) sms = 148;
    if (sms > NTILES) sms = NTILES;

    cudaFuncSetAttribute(lfm_kernel, cudaFuncAttributeMaxDynamicSharedMemorySize, SMEM_TOTAL);
    lfm_kernel<<<sms, THREADS, SMEM_TOTAL>>>(state, W, b, out);
}

// round 6
// speedup vs baseline: 1.1138x; 1.1138x over previous
#include <cuda_runtime.h>
#include <cuda_fp16.h>
#include <cstdint>

#define THREADS 512
static constexpr int BATCH  = 131072;
static constexpr int DDIM   = 128;
static constexpr int TILE_M = 128;
static constexpr int NTILES = BATCH / TILE_M;   // 1024
static constexpr int PITCH  = 272;              // 128 fp16 (256B) + 16B pad -> conflict-free ldmatrix
static constexpr int ASEG   = 32 * PITCH;       // 8704B: one 32-row group buffer

// ---- SMEM layout (bytes). A: 4 groups x 2 buffers (group-private); B single fp16. ----
static constexpr int SM_A    = 0;               // 4 * 2 * 8704 = 69632
static constexpr int SM_B    = 69632;           // 256 x PITCH = 69632
static constexpr int SM_BIAS = 139264;          // 256 floats = 1024
static constexpr int SMEM_TOTAL = 140288;

// ---------------- helpers ----------------
__device__ __forceinline__ uint32_t smem_u32(const void* p){
    uint32_t a;
    asm("{ .reg .u64 t; cvta.to.shared.u64 t, %1; cvt.u32.u64 %0, t; }" : "=r"(a) : "l"(p));
    return a;
}
__device__ __forceinline__ void ldsm4(uint32_t* r, uint32_t addr){
    asm volatile("ldmatrix.sync.aligned.m8n8.x4.shared.b16 {%0,%1,%2,%3}, [%4];"
        : "=r"(r[0]), "=r"(r[1]), "=r"(r[2]), "=r"(r[3]) : "r"(addr));
}
__device__ __forceinline__ void mma16816(float* c, const uint32_t* a, uint32_t b0, uint32_t b1){
    asm("mma.sync.aligned.m16n8k16.row.col.f32.f16.f16.f32 "
        "{%0,%1,%2,%3}, {%4,%5,%6,%7}, {%8,%9}, {%0,%1,%2,%3};"
        : "+f"(c[0]), "+f"(c[1]), "+f"(c[2]), "+f"(c[3])
        : "r"(a[0]), "r"(a[1]), "r"(a[2]), "r"(a[3]), "r"(b0), "r"(b1));
}
__device__ __forceinline__ uint32_t pack_h2(float lo, float hi){
    __half2 h = __floats2half2_rn(lo, hi);
    return *reinterpret_cast<uint32_t*>(&h);
}
__device__ __forceinline__ void group_bar(int id){
    asm volatile("bar.sync %0, 128;" :: "r"(id) : "memory");
}

// ---------------- group tile helpers (each wm-group owns 32 rows) ----------------
// gt in [0,128): thread index within the group. Each thread handles 8 float4.
__device__ __forceinline__ void prefetch_group(const float* __restrict__ state, int t, int wm, int gt, float4* v){
    const float4* p = reinterpret_cast<const float4*>(state)
                    + (size_t)t * (TILE_M * DDIM / 4) + (size_t)(wm * 32) * (DDIM / 4);
    #pragma unroll
    for (int k = 0; k < 8; k++) v[k] = p[gt + 128 * k];
}

__device__ __forceinline__ void convert_group(char* sm, uint32_t aseg_off, int gt, const float4* v){
    #pragma unroll
    for (int k = 0; k < 8; k++){
        int j  = gt + 128 * k;                // float4 index within 32x128 group slice
        int r  = j >> 5;                      // local row [0,32)
        int cb = (j & 31) * 8;                // byte col within 256B of fp16 data
        uint32_t off = aseg_off + (uint32_t)r * PITCH + cb;
        float4 f = v[k];
        uint32_t h0 = pack_h2(f.x, f.y);
        uint32_t h1 = pack_h2(f.z, f.w);
        *reinterpret_cast<uint2*>(sm + off) = make_uint2(h0, h1);
    }
}

// ---------------- kernel ----------------
__global__ void __launch_bounds__(THREADS, 1)
lfm_kernel(const float* __restrict__ state, const float* __restrict__ Wt,
           const float* __restrict__ bias,  float* __restrict__ out)
{
    extern __shared__ char sm[];
    uint32_t sbase = smem_u32(sm);
    const int tid  = threadIdx.x;
    const int wid  = tid >> 5;
    const int lane = tid & 31;
    const int wm   = wid & 3;       // warp m-block (32 rows each) == pipeline group
    const int wn   = wid >> 2;      // warp n-block (64 cols each)
    const int gt   = wn * 32 + lane;// thread index within group [0,128)

    // ---- one-time: W[n][o][d] -> fp16 B smem (row index = o*128+n, k=d), bias to smem ----
    for (int idx = tid; idx < 128 * 128; idx += THREADS){
        int n = idx >> 7, d = idx & 127;
        #pragma unroll
        for (int o = 0; o < 2; o++){
            float w = Wt[(size_t)n * 256 + o * 128 + d];
            uint32_t off = (uint32_t)(o * 128 + n) * PITCH + d * 2;
            *reinterpret_cast<__half*>(sm + SM_B + off) = __float2half_rn(w);
        }
    }
    for (int idx = tid; idx < 256; idx += THREADS){
        int o = idx >> 7, n = idx & 127;
        reinterpret_cast<float*>(sm + SM_BIAS)[idx] = bias[n * 2 + o];
    }

    // per-lane ldmatrix sub-offsets
    const uint32_t aoff = (uint32_t)((lane & 7) + ((lane >> 3) & 1) * 8) * PITCH + ((lane >> 4) & 1) * 16;
    const uint32_t boff = (uint32_t)((lane & 7) + ((lane >> 4) & 1) * 8) * PITCH + ((lane >> 3) & 1) * 16;
    const uint32_t aseg0 = (uint32_t)(SM_A + wm * 2 * ASEG);         // group buf 0 offset
    const uint32_t baseB = sbase + SM_B + (uint32_t)(wn * 64) * PITCH + boff;

    const int bid = blockIdx.x, grid = gridDim.x;
    const int nt  = (NTILES - bid + grid - 1) / grid;   // >= 1 since grid <= NTILES

    // Prologue: load + convert this group's slice of tile 0 into its buffer 0
    float4 v[8];
    prefetch_group(state, bid, wm, gt, v);
    convert_group(sm, aseg0, gt, v);
    __syncthreads();   // covers W/bias init + all groups' first convert

    // Bias fragments -> registers (constant across tiles)
    const int o_half = wn >> 1;
    float bR0[8], bR1[8];
    {
        const float* bias_sm = reinterpret_cast<const float*>(sm + SM_BIAS);
        #pragma unroll
        for (int nj = 0; nj < 8; nj++){
            int cgb = (wn & 1) * 64 + nj * 8 + 2 * (lane & 3) + (o_half << 7);
            bR0[nj] = bias_sm[cgb];
            bR1[nj] = bias_sm[cgb + 1];
        }
    }

    const size_t out_half = (size_t)BATCH * DDIM;
    const int barid = 1 + wm;

    int cur = 0;
    for (int i = 0; i < nt; i++){
        const int  t   = bid + i * grid;
        const bool nxt = (i + 1) < nt;

        const uint32_t bA = sbase + aseg0 + (uint32_t)cur * ASEG + aoff;

        float acc[2][8][4];
        #pragma unroll
        for (int mt = 0; mt < 2; mt++)
            #pragma unroll
            for (int nj = 0; nj < 8; nj++)
                #pragma unroll
                for (int e = 0; e < 4; e++) acc[mt][nj][e] = 0.f;

        // ---- K loop: 8 steps of k16, single fp16 term ----
        #pragma unroll
        for (int ks = 0; ks < 8; ks++){
            uint32_t a0[4], a1[4];
            ldsm4(a0, bA + ks * 32);
            ldsm4(a1, bA + 16 * PITCH + ks * 32);
            #pragma unroll
            for (int np = 0; np < 4; np++){        // pairs of n8 tiles
                uint32_t bw[4];
                ldsm4(bw, baseB + (uint32_t)(np * 16) * PITCH + ks * 32);
                mma16816(acc[0][2*np],   a0, bw[0], bw[1]);
                mma16816(acc[1][2*np],   a1, bw[0], bw[1]);
                mma16816(acc[0][2*np+1], a0, bw[2], bw[3]);
                mma16816(acc[1][2*np+1], a1, bw[2], bw[3]);
            }
        }

        // Prefetch next tile's group slice; DRAM latency hidden behind epilogue stores.
        if (nxt) prefetch_group(state, t + grid, wm, gt, v);

        // ---- epilogue: bias + direct STG.64. Warp covers rows [wm*32,+32), cols [wn*64,+64). ----
        {
            const int colw  = (wn & 1) * 64;
            const int rbase = wm * 32 + (lane >> 2);
            float* outp = out + (o_half ? out_half : 0) + ((size_t)t * TILE_M) * DDIM;
            #pragma unroll
            for (int mt = 0; mt < 2; mt++){
                #pragma unroll
                for (int nj = 0; nj < 8; nj++){
                    const int cg = colw + nj * 8 + 2 * (lane & 3);
                    float b0 = bR0[nj], b1 = bR1[nj];
                    float* p0 = outp + (size_t)(rbase + mt * 16) * DDIM + cg;
                    float* p1 = p0 + 8 * DDIM;
                    *reinterpret_cast<float2*>(p0) = make_float2(acc[mt][nj][0] + b0, acc[mt][nj][1] + b1);
                    *reinterpret_cast<float2*>(p1) = make_float2(acc[mt][nj][2] + b0, acc[mt][nj][3] + b1);
                }
            }
        }

        // Refill this group's other buffer; group-scoped barrier only.
        if (nxt){
            convert_group(sm, aseg0 + (uint32_t)(cur ^ 1) * ASEG, gt, v);
            group_bar(barid);
        }
        cur ^= 1;
    }
}

extern "C" void kernel_launch(void* const* d_in, const int* in_sizes, int n_in,
                              void* d_out, int out_size){
    (void)in_sizes; (void)n_in; (void)out_size;
    const float* state = (const float*)d_in[0];
    const float* W     = (const float*)d_in[1];
    const float* b     = (const float*)d_in[2];
    float* out = (float*)d_out;

    int dev = 0, sms = 148;
    cudaGetDevice(&dev);
    cudaDeviceGetAttribute(&sms, cudaDevAttrMultiProcessorCount, dev);
    if (sms < 1) sms = 148;
    if (sms > NTILES) sms = NTILES;

    cudaFuncSetAttribute(lfm_kernel, cudaFuncAttributeMaxDynamicSharedMemorySize, SMEM_TOTAL);
    lfm_kernel<<<sms, THREADS, SMEM_TOTAL>>>(state, W, b, out);
}

// round 7
// speedup vs baseline: 1.1938x; 1.0718x over previous
#include <cuda_runtime.h>
#include <cuda_fp16.h>
#include <cstdint>

#define THREADS 512
static constexpr int BATCH  = 131072;
static constexpr int DDIM   = 128;
static constexpr int TILE_M = 128;
static constexpr int NTILES = BATCH / TILE_M;   // 1024
static constexpr int PITCH  = 272;              // 128 fp16 (256B) + 16B pad -> conflict-free ldmatrix
static constexpr int ASEG   = 32 * PITCH;       // 8704B: one 32-row group buffer

// ---- SMEM layout (bytes). A: 4 groups x 2 buffers (group-private); B single fp16. ----
static constexpr int SM_A    = 0;               // 4 * 2 * 8704 = 69632
static constexpr int SM_B    = 69632;           // 256 x PITCH = 69632
static constexpr int SM_BIAS = 139264;          // 256 floats = 1024
static constexpr int SMEM_TOTAL = 140288;

// ---------------- helpers ----------------
__device__ __forceinline__ uint32_t smem_u32(const void* p){
    uint32_t a;
    asm("{ .reg .u64 t; cvta.to.shared.u64 t, %1; cvt.u32.u64 %0, t; }" : "=r"(a) : "l"(p));
    return a;
}
__device__ __forceinline__ void ldsm4(uint32_t* r, uint32_t addr){
    asm volatile("ldmatrix.sync.aligned.m8n8.x4.shared.b16 {%0,%1,%2,%3}, [%4];"
        : "=r"(r[0]), "=r"(r[1]), "=r"(r[2]), "=r"(r[3]) : "r"(addr));
}
__device__ __forceinline__ void mma16816(float* c, const uint32_t* a, uint32_t b0, uint32_t b1){
    asm("mma.sync.aligned.m16n8k16.row.col.f32.f16.f16.f32 "
        "{%0,%1,%2,%3}, {%4,%5,%6,%7}, {%8,%9}, {%0,%1,%2,%3};"
        : "+f"(c[0]), "+f"(c[1]), "+f"(c[2]), "+f"(c[3])
        : "r"(a[0]), "r"(a[1]), "r"(a[2]), "r"(a[3]), "r"(b0), "r"(b1));
}
__device__ __forceinline__ uint32_t pack_h2(float lo, float hi){
    __half2 h = __floats2half2_rn(lo, hi);
    return *reinterpret_cast<uint32_t*>(&h);
}
__device__ __forceinline__ void group_bar(int id){
    asm volatile("bar.sync %0, 128;" :: "r"(id) : "memory");
}

// ---------------- group tile helpers (each group owns 32 rows of the tile) ----------------
// gt in [0,128): thread index within the group. Each thread handles 8 float4.
__device__ __forceinline__ void prefetch_group(const float* __restrict__ state, int t, int wm, int gt, float4* v){
    const float4* p = reinterpret_cast<const float4*>(state)
                    + (size_t)t * (TILE_M * DDIM / 4) + (size_t)(wm * 32) * (DDIM / 4);
    #pragma unroll
    for (int k = 0; k < 8; k++) v[k] = p[gt + 128 * k];
}

__device__ __forceinline__ void convert_group(char* sm, uint32_t aseg_off, int gt, const float4* v){
    #pragma unroll
    for (int k = 0; k < 8; k++){
        int j  = gt + 128 * k;                // float4 index within 32x128 group slice
        int r  = j >> 5;                      // local row [0,32)
        int cb = (j & 31) * 8;                // byte col within 256B of fp16 data
        uint32_t off = aseg_off + (uint32_t)r * PITCH + cb;
        float4 f = v[k];
        uint32_t h0 = pack_h2(f.x, f.y);
        uint32_t h1 = pack_h2(f.z, f.w);
        *reinterpret_cast<uint2*>(sm + off) = make_uint2(h0, h1);
    }
}

// ---------------- kernel ----------------
__global__ void __launch_bounds__(THREADS, 1)
lfm_kernel(const float* __restrict__ state, const float* __restrict__ Wt,
           const float* __restrict__ bias,  float* __restrict__ out)
{
    extern __shared__ char sm[];
    uint32_t sbase = smem_u32(sm);
    const int tid  = threadIdx.x;
    const int wid  = tid >> 5;
    const int lane = tid & 31;
    // Group = contiguous warp quartet (wid>>2): its 4 warps land on SMSPs 0..3,
    // so every SMSP hosts one warp from each pipeline group (phase interleaving).
    const int wm   = wid >> 2;      // pipeline group / m-block (32 rows each)
    const int wn   = wid & 3;       // warp n-block (64 cols each)
    const int gt   = tid & 127;     // thread index within group [0,128)

    // ---- one-time: W[n][o][d] -> fp16 B smem (row index = o*128+n, k=d), bias to smem ----
    for (int idx = tid; idx < 128 * 128; idx += THREADS){
        int n = idx >> 7, d = idx & 127;
        #pragma unroll
        for (int o = 0; o < 2; o++){
            float w = Wt[(size_t)n * 256 + o * 128 + d];
            uint32_t off = (uint32_t)(o * 128 + n) * PITCH + d * 2;
            *reinterpret_cast<__half*>(sm + SM_B + off) = __float2half_rn(w);
        }
    }
    for (int idx = tid; idx < 256; idx += THREADS){
        int o = idx >> 7, n = idx & 127;
        reinterpret_cast<float*>(sm + SM_BIAS)[idx] = bias[n * 2 + o];
    }

    // per-lane ldmatrix sub-offsets
    const uint32_t aoff = (uint32_t)((lane & 7) + ((lane >> 3) & 1) * 8) * PITCH + ((lane >> 4) & 1) * 16;
    const uint32_t boff = (uint32_t)((lane & 7) + ((lane >> 4) & 1) * 8) * PITCH + ((lane >> 3) & 1) * 16;
    const uint32_t aseg0 = (uint32_t)(SM_A + wm * 2 * ASEG);         // group buf 0 offset
    const uint32_t baseB = sbase + SM_B + (uint32_t)(wn * 64) * PITCH + boff;

    const int bid = blockIdx.x, grid = gridDim.x;
    const int nt  = (NTILES - bid + grid - 1) / grid;   // >= 1 since grid <= NTILES

    // Prologue: load + convert this group's slice of tile 0 into its buffer 0
    float4 v[8];
    prefetch_group(state, bid, wm, gt, v);
    convert_group(sm, aseg0, gt, v);
    __syncthreads();   // covers W/bias init + all groups' first convert

    // Bias fragments -> registers (constant across tiles)
    const int o_half = wn >> 1;
    float bR0[8], bR1[8];
    {
        const float* bias_sm = reinterpret_cast<const float*>(sm + SM_BIAS);
        #pragma unroll
        for (int nj = 0; nj < 8; nj++){
            int cgb = (wn & 1) * 64 + nj * 8 + 2 * (lane & 3) + (o_half << 7);
            bR0[nj] = bias_sm[cgb];
            bR1[nj] = bias_sm[cgb + 1];
        }
    }

    const size_t out_half = (size_t)BATCH * DDIM;
    const int barid = 1 + wm;

    int cur = 0;
    for (int i = 0; i < nt; i++){
        const int  t   = bid + i * grid;
        const bool nxt = (i + 1) < nt;

        const uint32_t bA = sbase + aseg0 + (uint32_t)cur * ASEG + aoff;

        float acc[2][8][4];
        #pragma unroll
        for (int mt = 0; mt < 2; mt++)
            #pragma unroll
            for (int nj = 0; nj < 8; nj++)
                #pragma unroll
                for (int e = 0; e < 4; e++) acc[mt][nj][e] = 0.f;

        // ---- K loop: 8 steps of k16, single fp16 term ----
        #pragma unroll
        for (int ks = 0; ks < 8; ks++){
            uint32_t a0[4], a1[4];
            ldsm4(a0, bA + ks * 32);
            ldsm4(a1, bA + 16 * PITCH + ks * 32);
            #pragma unroll
            for (int np = 0; np < 4; np++){        // pairs of n8 tiles
                uint32_t bw[4];
                ldsm4(bw, baseB + (uint32_t)(np * 16) * PITCH + ks * 32);
                mma16816(acc[0][2*np],   a0, bw[0], bw[1]);
                mma16816(acc[1][2*np],   a1, bw[0], bw[1]);
                mma16816(acc[0][2*np+1], a0, bw[2], bw[3]);
                mma16816(acc[1][2*np+1], a1, bw[2], bw[3]);
            }
        }

        // Prefetch next tile's group slice; DRAM latency hidden behind epilogue stores.
        if (nxt) prefetch_group(state, t + grid, wm, gt, v);

        // ---- epilogue: bias + direct STG.64. Warp covers rows [wm*32,+32), cols [wn*64,+64). ----
        {
            const int colw  = (wn & 1) * 64;
            const int rbase = wm * 32 + (lane >> 2);
            float* outp = out + (o_half ? out_half : 0) + ((size_t)t * TILE_M) * DDIM;
            #pragma unroll
            for (int mt = 0; mt < 2; mt++){
                #pragma unroll
                for (int nj = 0; nj < 8; nj++){
                    const int cg = colw + nj * 8 + 2 * (lane & 3);
                    float b0 = bR0[nj], b1 = bR1[nj];
                    float* p0 = outp + (size_t)(rbase + mt * 16) * DDIM + cg;
                    float* p1 = p0 + 8 * DDIM;
                    *reinterpret_cast<float2*>(p0) = make_float2(acc[mt][nj][0] + b0, acc[mt][nj][1] + b1);
                    *reinterpret_cast<float2*>(p1) = make_float2(acc[mt][nj][2] + b0, acc[mt][nj][3] + b1);
                }
            }
        }

        // Refill this group's other buffer; group-scoped barrier only.
        if (nxt){
            convert_group(sm, aseg0 + (uint32_t)(cur ^ 1) * ASEG, gt, v);
            group_bar(barid);
        }
        cur ^= 1;
    }
}

extern "C" void kernel_launch(void* const* d_in, const int* in_sizes, int n_in,
                              void* d_out, int out_size){
    (void)in_sizes; (void)n_in; (void)out_size;
    const float* state = (const float*)d_in[0];
    const float* W     = (const float*)d_in[1];
    const float* b     = (const float*)d_in[2];
    float* out = (float*)d_out;

    int dev = 0, sms = 148;
    cudaGetDevice(&dev);
    cudaDeviceGetAttribute(&sms, cudaDevAttrMultiProcessorCount, dev);
    if (sms < 1) sms = 148;
    if (sms > NTILES) sms = NTILES;

    cudaFuncSetAttribute(lfm_kernel, cudaFuncAttributeMaxDynamicSharedMemorySize, SMEM_TOTAL);
    lfm_kernel<<<sms, THREADS, SMEM_TOTAL>>>(state, W, b, out);
}